// round 15
// baseline (speedup 1.0000x reference)
#include <cuda_runtime.h>
#include <cuda_bf16.h>
#include <cstdint>

// CTC forward negative log-likelihood (keras ctc_batch_cost semantics).
// B=128, T=1024, V=512, L=128, S=2L+1=257, blank=V-1.
//
// Round-15 design ("composed 2-step + staged gather buffer"):
//  - R14 scaffold: 1 CTA/batch, 288 threads, thread s=tid owns state s,
//    composed 2-step update (5-term weighted logsumexp, linear path weights),
//    ONE __syncthreads per 2 steps, cp.async D=16 row ring, wait_group<4>.
//  - NEW: consumers no longer gather scattered from the 2KB rows. Gather
//    threads (tid 128..255, one per label; separate warps from the cp.async
//    producers tid<128) stage Y[row][lab_l] for two rows per iteration into a
//    double-buffered 264-float shared array Gh (labels 0..127 + blank slots),
//    TWO iterations ahead (rows t+4,t+5 — complete & visible under the
//    D=16/wait<4> invariant: at iteration t, rows <= t+7 are complete).
//    Consumers prefetch P0/P1/P2/Qs via 4 conflict-free indexed LDS from Gh.
//    Scattered-LDS crossbar cost drops ~180 -> ~32 cyc/iter.
//  - A0 (own alpha) carried in a register (aPrev) — one fewer LDS on chain.
//  - Pipeline: Gh[i&1] written at iter i (targets i+2), registers loaded at
//    i+1, consumed at i+2; barriers separate all write/read pairs (no WAR).

#define NEGV (-1e30f)
#define EPSV (1e-7f)
#define LN2F (0.6931471805599453f)

constexpr int Bc = 128;
constexpr int Tc = 1024;
constexpr int Vc = 512;
constexpr int Lc = 128;
constexpr int Sc = 257;     // 2L+1
constexpr int D  = 16;      // ring stages (32KB)
constexpr int NT = 288;     // 9 warps

__device__ __forceinline__ float ex2f(float x) {
    float r; asm("ex2.approx.f32 %0, %1;" : "=f"(r) : "f"(x)); return r;
}
__device__ __forceinline__ float lg2f(float x) {
    float r; asm("lg2.approx.f32 %0, %1;" : "=f"(r) : "f"(x)); return r;
}
__device__ __forceinline__ void cp_async16(uint32_t saddr, const void* gptr) {
    asm volatile("cp.async.cg.shared.global [%0], [%1], 16;" :: "r"(saddr), "l"(gptr));
}
__device__ __forceinline__ void cp_commit() {
    asm volatile("cp.async.commit_group;");
}
template<int N>
__device__ __forceinline__ void cp_wait() {
    asm volatile("cp.async.wait_group %0;" :: "n"(N));
}

__global__ __launch_bounds__(NT, 1)
void ctc_forward_kernel(const int*   __restrict__ labels,     // [B, L]
                        const int*   __restrict__ lab_len,    // [B, 1]
                        const float* __restrict__ Y,          // [B, T, V]
                        const int*   __restrict__ in_len,     // [B, 1]
                        float*       __restrict__ out)        // [B, 1]
{
    __shared__ __align__(16) float rows[D][Vc];   // staged probability rows (32KB)
    __shared__ float As[2][Sc + 8];               // alpha: 4 front-pad + 257 + tail
    __shared__ float Gh[2][264];                  // gathered label probs:
                                                  // [buf][0..127]=row0 labels, [128]=row0 blank
                                                  // [buf][132..259]=row1 labels, [260]=row1 blank
    __shared__ int   lab_sh[Lc];

    const int b   = blockIdx.x;
    const int tid = threadIdx.x;

    if (tid < Lc) lab_sh[tid] = labels[b * Lc + tid];
    const int len = in_len[b];

    const bool active = (tid <= 256);
    const int  s      = tid;

    if (tid < 4) { As[0][tid] = NEGV; As[1][tid] = NEGV; }
    if (active) As[0][4 + s] = (s == 0) ? 0.0f : NEGV;    // log2 domain

    const float* __restrict__ Yb = Y + (size_t)b * Tc * Vc;
    const bool producer = (tid < 128);                    // cp.async warps 0-3
    const bool gatherer = (tid >= 128 && tid < 256);      // gather warps 4-7
    const int  gid      = tid - 128;                      // label handled
    const uint32_t rows_sb = (uint32_t)__cvta_generic_to_shared(&rows[0][0]);

    // ---- prologue: stage rows 0..D-1 (2 rows per commit group, 8 groups) ----
    if (producer) {
        #pragma unroll
        for (int g = 0; g < D / 2; g++) {
            #pragma unroll
            for (int r = 0; r < 2; r++) {
                const int j  = 2 * g + r;
                const int tr = (j < len) ? j : (len > 0 ? len - 1 : 0);
                cp_async16(rows_sb + (uint32_t)j * 2048u + (uint32_t)tid * 16u,
                           Yb + (size_t)tr * Vc + tid * 4);
            }
            cp_commit();
        }
        cp_wait<4>();                 // groups 0..3 complete -> rows 0..7
    }
    __syncthreads();                  // labels, alpha0, rows 0..7 visible

    // ---- per-thread constants ----
    const int  blank = Vc - 1;
    const bool sOdd  = (s & 1) != 0;
    int  cls_s  = blank, cls_m1 = blank, cls_m2 = blank;
    bool cs_s = false, cs_m1 = false, cs_m2 = false;
    if (active) {
        if (sOdd) {
            cls_s  = lab_sh[(s - 1) >> 1];
            cls_m2 = (s >= 3) ? lab_sh[(s - 3) >> 1] : blank;
            cs_s   = (s >= 3) && (cls_s != cls_m2) && (cls_s != blank);
            cs_m2  = (s >= 5) && (lab_sh[(s - 3) >> 1] != lab_sh[(s - 5) >> 1])
                              && (cls_m2 != blank);
        } else {
            cls_m1 = (s >= 2) ? lab_sh[(s - 2) >> 1] : blank;
            cs_m1  = (s >= 4) && (lab_sh[(s - 2) >> 1] != lab_sh[(s - 4) >> 1])
                              && (cls_m1 != blank);
        }
    }
    const bool pm3 = cs_m1 || cs_s;       // W3 > 0 ?
    const bool pm4 = cs_s && cs_m2;       // W4 > 0 ?

    // Gh read indices (within a 264-float buffer): row0 at [0..128], row1 at [132..260]
    const int lg  = sOdd ? ((s - 1) >> 1) : (s >> 1);
    const int iP0 = sOdd ? lg : 128;
    const int iP1 = sOdd ? 128 : ((s >= 2) ? (lg - 1) : 128);
    const int iP2 = (sOdd && s >= 3) ? (lg - 1) : 128;
    const int iQ  = 132 + (sOdd ? lg : 128);

    // gatherer class
    const int cls_g = gatherer ? lab_sh[gid] : blank;

    // ---- prologue part 2: fill Gh buf[1] with rows 2,3 (read at i=0 for i=1) ----
    if (gatherer && 2 < len) {
        Gh[1][gid]       = rows[2 & (D - 1)][cls_g];
        Gh[1][132 + gid] = rows[3 & (D - 1)][cls_g];
    }
    if (tid == 256 && 2 < len) {
        Gh[1][128] = rows[2 & (D - 1)][blank];
        Gh[1][260] = rows[3 & (D - 1)][blank];
    }

    // initial registers for iteration 0 (rows 0,1 complete)
    float P0 = EPSV, P1 = EPSV, P2 = EPSV, Qs = EPSV;
    if (active) {
        P0 = rows[0][cls_s]  + EPSV;
        P1 = rows[0][cls_m1] + EPSV;
        P2 = rows[0][cls_m2] + EPSV;
        Qs = rows[1][cls_s]  + EPSV;
    }
    float aPrev = (s == 0) ? 0.0f : NEGV;     // alpha_t[s] carried in register
    __syncthreads();                          // publish Gh[1]

    // ---- main recursion: 2 composed steps per barrier ----
    int rd = 0;
    int t  = 0;
    for (; t + 1 < len; t += 2) {
        const int i = t >> 1;

        if (active) {
            // linear path weights (FMA/ALU only)
            const float W0 = P0;
            const float W1 = P0 + P1;
            const float W2 = cs_s ? (W1 + P2) : P1;
            const float W3 = (cs_m1 ? P1 : 0.0f) + (cs_s ? P2 : 0.0f);
            const float W4 = pm4 ? P2 : 0.0f;

            const float* __restrict__ A = &As[rd][4];   // A[i] = alpha_t[i]
            const float A0 = aPrev;                     // own alpha (register)
            const float A1 = A[s - 1];
            const float A2 = A[s - 2];
            const float A3 = pm3 ? A[s - 3] : NEGV;     // mask zero-weight terms
            const float A4 = pm4 ? A[s - 4] : NEGV;

            const float m = fmaxf(fmaxf(fmaxf(A0, A1), fmaxf(A2, A3)), A4);
            const float x0 = ex2f(A0 - m);
            const float x1 = ex2f(A1 - m);
            const float x2 = ex2f(A2 - m);
            const float x3 = ex2f(A3 - m);
            const float x4 = ex2f(A4 - m);
            const float sum = (W0 * x0 + W1 * x1) + (W2 * x2 + (W3 * x3 + W4 * x4));
            const float n = m + lg2f(sum * Qs);
            As[rd ^ 1][4 + s] = n;
            aPrev = n;
        }

        // gather for iteration i+2 (rows t+4,t+5) into buf i&1.
        // Safety: at iteration t, rows <= t+7 are complete (wait<4>, D=16)
        // and visible (barrier). Slot (t+5)&15 was written (possibly clamped)
        // whenever t+4 < len.
        if (gatherer && (t + 4) < len) {
            Gh[i & 1][gid]       = rows[(t + 4) & (D - 1)][cls_g];
            Gh[i & 1][132 + gid] = rows[(t + 5) & (D - 1)][cls_g];
        }
        if (tid == 256 && (t + 4) < len) {
            Gh[i & 1][128] = rows[(t + 4) & (D - 1)][blank];
            Gh[i & 1][260] = rows[(t + 5) & (D - 1)][blank];
        }

        // register prefetch for iteration i+1 from buf (i&1)^1 (rows t+2,t+3),
        // written at i-1 and published by i-1's barrier. Conflict-free LDS.
        if (active) {
            const float* __restrict__ G = Gh[(i & 1) ^ 1];
            if (t + 3 < len) {
                P0 = G[iP0] + EPSV;
                P1 = G[iP1] + EPSV;
                P2 = G[iP2] + EPSV;
                Qs = G[iQ]  + EPSV;
            } else if (t + 2 < len) {
                P0 = G[iP0] + EPSV;     // odd tail: p_s at row t+2
            }
        }

        if (producer) cp_wait<4>();   // all but newest 4 groups complete
        __syncthreads();              // publish alpha_{t+2}, Gh[i&1]; retire slots
        if (producer && (t + D) < len) {
            #pragma unroll
            for (int r = 0; r < 2; r++) {
                const int j  = t + D + r;
                const int tr = (j < len) ? j : (len - 1);
                cp_async16(rows_sb + (uint32_t)(j & (D - 1)) * 2048u + (uint32_t)tid * 16u,
                           Yb + (size_t)tr * Vc + tid * 4);
            }
            cp_commit();
        }
        rd ^= 1;
    }

    // ---- odd tail: one single step (len odd) ----
    if (t < len) {
        if (active) {
            const float* __restrict__ A = &As[rd][4];
            const float A0 = aPrev;
            const float A1 = A[s - 1];
            const float A2 = cs_s ? A[s - 2] : NEGV;
            const float m  = fmaxf(fmaxf(A0, A1), A2);
            const float sum = ex2f(A0 - m) + ex2f(A1 - m) + ex2f(A2 - m);
            As[rd ^ 1][4 + s] = m + lg2f(sum * P0);   // P0 = p_s at row t
        }
        __syncthreads();
        rd ^= 1;
    }

    // ---- final: loss = -ln2 * logaddexp2(alpha[2*lab], alpha[2*lab-1]) ----
    if (tid == 0) {
        const int   ll = lab_len[b];
        const float aL = As[rd][4 + 2 * ll];
        const float aP = As[rd][4 + 2 * ll - 1];
        const float mm = fmaxf(aL, aP);
        const float ql = fminf(aL, aP);
        out[b] = -LN2F * (mm + lg2f(1.0f + ex2f(ql - mm)));
    }
}

extern "C" void kernel_launch(void* const* d_in, const int* in_sizes, int n_in,
                              void* d_out, int out_size) {
    const int*   labels  = (const int*)d_in[0];   // true_labels [B, L]
    const int*   lab_len = (const int*)d_in[1];   // true_lengths [B, 1]
    const float* Y       = (const float*)d_in[2]; // predicted_labels [B, T, V]
    const int*   in_len  = (const int*)d_in[3];   // predicted_lengths [B, 1]
    float*       out     = (float*)d_out;         // [B, 1]

    ctc_forward_kernel<<<Bc, NT>>>(labels, lab_len, Y, in_len, out);
}